// round 16
// baseline (speedup 1.0000x reference)
#include <cuda_runtime.h>
#include <cuda_bf16.h>
#include <cstdint>
#include <math.h>

#define NS    4096
#define NTOT  8192
#define DIM   512
#define BM    128
#define BN    128
#define BKB   128             // k-chunk in bytes (= 128 int8 elems)
#define NKC   (DIM / BKB)     // 4 k-chunks
#define SQRT2F 1.41421356237f
#define ASTAGE 16384          // 128 rows * 128B
#define STAGE_BYTES (2 * ASTAGE)
#define NSTAGE 3
#define SMEM_DYN (NSTAGE * STAGE_BYTES)   // 96KB
#define NOFF  (64 * 63 / 2)   // strict lower-triangular (off-diag) tiles: 2016
#define NTILE (NOFF + 64)     // + 64 diagonal tiles, scheduled LAST

// ---------------- scratch (__device__ globals; no allocation allowed) -------
__device__ __align__(16) uint8_t g_Yq[NTOT * DIM];   // int8 quantized rows
__device__ float g_rs[NTOT];        // per-row dequant scale (rowmax/127)
__device__ float g_inv_norm[NTOT];
__device__ float g_row_exp[NTOT];
__device__ float g_posdot[NS];
__device__ float g_S[DIM];          // zeroed by previous call's tail (static-init 0 first)
__device__ float g_acc[3];          // idem
__device__ unsigned int g_done;     // idem

// ---------------- PTX helpers (baseline PTX only) ---------------------------
__device__ __forceinline__ uint32_t smem_u32(const void* p) {
    uint32_t a;
    asm("{ .reg .u64 t; cvta.to.shared.u64 t, %1; cvt.u32.u64 %0, t; }" : "=r"(a) : "l"(p));
    return a;
}
__device__ __forceinline__ void cp16(uint32_t dst, const void* src) {
    asm volatile("cp.async.cg.shared.global [%0], [%1], 16;" :: "r"(dst), "l"(src) : "memory");
}
__device__ __forceinline__ void ldm_x4(uint32_t* r, uint32_t addr) {
    asm volatile("ldmatrix.sync.aligned.m8n8.x4.shared.b16 {%0,%1,%2,%3}, [%4];"
                 : "=r"(r[0]), "=r"(r[1]), "=r"(r[2]), "=r"(r[3]) : "r"(addr));
}
__device__ __forceinline__ void mma_s8(int* d, const uint32_t* a, const uint32_t* b) {
    asm volatile(
        "mma.sync.aligned.m16n8k32.row.col.s32.s8.s8.s32 "
        "{%0,%1,%2,%3}, {%4,%5,%6,%7}, {%8,%9}, {%0,%1,%2,%3};"
        : "+r"(d[0]), "+r"(d[1]), "+r"(d[2]), "+r"(d[3])
        : "r"(a[0]), "r"(a[1]), "r"(a[2]), "r"(a[3]), "r"(b[0]), "r"(b[1]));
}
__device__ __forceinline__ uint32_t pack_s8x4(float a, float b, float c, float d) {
    int q0 = __float2int_rn(a), q1 = __float2int_rn(b);
    int q2 = __float2int_rn(c), q3 = __float2int_rn(d);
    return (uint32_t)(q0 & 0xff) | ((uint32_t)(q1 & 0xff) << 8) |
           ((uint32_t)(q2 & 0xff) << 16) | ((uint32_t)(q3 & 0xff) << 24);
}
// SW128 swizzle for 128B rows: row r, 16B chunk c (0..7). Bank16 = c ^ (r&7):
// distinct across any 8 consecutive rows -> conflict-free ldmatrix phases.
__device__ __forceinline__ uint32_t swz(int r, int c) {
    return (uint32_t)(r * 128 + ((c ^ (r & 7)) << 4));
}
__device__ __forceinline__ const float* row_ptr(const float* x1, const float* x2, int r) {
    return (r < NS) ? (x1 + (size_t)r * DIM) : (x2 + (size_t)(r - NS) * DIM);
}

// ---------------- kernel 1: norms + int8 Y + posdot + fused colsum ----------
// One sample per warp: rows (s, s+NS) from x1[s], x2[s], each read once.
__global__ void prep_kernel(const float* __restrict__ x1, const float* __restrict__ x2) {
    __shared__ float sY[16][DIM];
    const int wid  = threadIdx.x >> 5;
    const int lane = threadIdx.x & 31;
    const int s    = blockIdx.x * 8 + wid;          // sample 0..4095

    const float4* xa = (const float4*)(x1 + (size_t)s * DIM);
    const float4* xb = (const float4*)(x2 + (size_t)s * DIM);
    float4 va[4], vb[4];
    #pragma unroll
    for (int c = 0; c < 4; c++) {
        va[c] = xa[lane + 32 * c];
        vb[c] = xb[lane + 32 * c];
    }
    float sa = 0.f, sb = 0.f, pd = 0.f;
    #pragma unroll
    for (int c = 0; c < 4; c++) {
        sa += va[c].x * va[c].x + va[c].y * va[c].y + va[c].z * va[c].z + va[c].w * va[c].w;
        sb += vb[c].x * vb[c].x + vb[c].y * vb[c].y + vb[c].z * vb[c].z + vb[c].w * vb[c].w;
        pd += va[c].x * vb[c].x + va[c].y * vb[c].y + va[c].z * vb[c].z + va[c].w * vb[c].w;
    }
    #pragma unroll
    for (int o = 16; o; o >>= 1) {
        sa += __shfl_xor_sync(0xffffffffu, sa, o);
        sb += __shfl_xor_sync(0xffffffffu, sb, o);
        pd += __shfl_xor_sync(0xffffffffu, pd, o);
    }
    float inva = rsqrtf(sa), invb = rsqrtf(sb);
    if (lane == 0) {
        g_inv_norm[s]      = inva;
        g_inv_norm[s + NS] = invb;
        g_row_exp[s]       = 0.f;
        g_row_exp[s + NS]  = 0.f;
        g_posdot[s]        = pd;
    }
    inva = __shfl_sync(0xffffffffu, inva, 0);
    invb = __shfl_sync(0xffffffffu, invb, 0);
    const float ka = inva * SQRT2F, kb = invb * SQRT2F;

    // per-row max(|y|) for int8 scaling
    float ma = 0.f, mb = 0.f;
    #pragma unroll
    for (int c = 0; c < 4; c++) {
        ma = fmaxf(ma, fmaxf(fmaxf(fabsf(va[c].x), fabsf(va[c].y)),
                             fmaxf(fabsf(va[c].z), fabsf(va[c].w))));
        mb = fmaxf(mb, fmaxf(fmaxf(fabsf(vb[c].x), fabsf(vb[c].y)),
                             fmaxf(fabsf(vb[c].z), fabsf(vb[c].w))));
    }
    #pragma unroll
    for (int o = 16; o; o >>= 1) {
        ma = fmaxf(ma, __shfl_xor_sync(0xffffffffu, ma, o));
        mb = fmaxf(mb, __shfl_xor_sync(0xffffffffu, mb, o));
    }
    ma *= ka; mb *= kb;                     // max|y| per row
    const float qa = 127.f / ma, qb = 127.f / mb;
    if (lane == 0) {
        g_rs[s]      = ma * (1.f / 127.f);
        g_rs[s + NS] = mb * (1.f / 127.f);
    }

    uint32_t* ya = (uint32_t*)(g_Yq + (size_t)s * DIM);
    uint32_t* yb = (uint32_t*)(g_Yq + (size_t)(s + NS) * DIM);
    float4* s4a = (float4*)sY[wid * 2];
    float4* s4b = (float4*)sY[wid * 2 + 1];
    #pragma unroll
    for (int c = 0; c < 4; c++) {
        float4 yA = make_float4(va[c].x * ka, va[c].y * ka, va[c].z * ka, va[c].w * ka);
        float4 yB = make_float4(vb[c].x * kb, vb[c].y * kb, vb[c].z * kb, vb[c].w * kb);
        s4a[lane + 32 * c] = yA;
        s4b[lane + 32 * c] = yB;
        ya[lane + 32 * c] = pack_s8x4(yA.x * qa, yA.y * qa, yA.z * qa, yA.w * qa);
        yb[lane + 32 * c] = pack_s8x4(yB.x * qb, yB.y * qb, yB.z * qb, yB.w * qb);
    }
    __syncthreads();
    #pragma unroll
    for (int col = threadIdx.x; col < DIM; col += 256) {
        float t = 0.f;
        #pragma unroll
        for (int r = 0; r < 16; r++) t += sY[r][col];
        atomicAdd(&g_S[col], t);
    }
}

// ---------------- kernel 2: int8 IMMA GEMM on triangular tiles --------------
// R13 structure (occ-2, 3-stage, straight-line); s32 accum, scaled epilogue.
__global__ __launch_bounds__(256, 2) void gemm_kernel() {
    extern __shared__ __align__(128) char smem[];
    __shared__ float red[BM];
    __shared__ float cred[BN];
    __shared__ float sRS[BM];
    __shared__ float sCS[BN];
    const uint32_t sb = smem_u32(smem);
    const int tid  = threadIdx.x, lane = tid & 31, wid = tid >> 5;
    const int wm   = wid & 3, wn = wid >> 2;

    const int k = blockIdx.x;
    int bx, by;
    const bool offdiag = (k < NOFF);
    if (offdiag) {
        bx = (int)((sqrtf(8.0f * (float)k + 1.0f) + 1.0f) * 0.5f);
        while (bx * (bx - 1) / 2 > k)        bx--;
        while ((bx + 1) * bx / 2 <= k)       bx++;
        by = k - bx * (bx - 1) / 2;
    } else {
        bx = by = k - NOFF;
    }
    const int row0 = by * BM, col0 = bx * BN;
    const bool hasmask = (((bx ^ by) & 31) == 0);

    if (tid < BM) { sRS[tid] = g_rs[row0 + tid]; sCS[tid] = g_rs[col0 + tid]; }

    const int lr  = tid >> 1;
    const int lc0 = (tid & 1) * 4;
    const char* a_gsrc = (const char*)(g_Yq + (size_t)(row0 + lr) * DIM) + lc0 * 16;
    const char* b_gsrc = (const char*)(g_Yq + (size_t)(col0 + lr) * DIM) + lc0 * 16;
    uint32_t ad[4];
    #pragma unroll
    for (int i = 0; i < 4; i++) ad[i] = swz(lr, lc0 + i);

    int acc[2][8][4];
    #pragma unroll
    for (int mi = 0; mi < 2; mi++)
        #pragma unroll
        for (int ni = 0; ni < 8; ni++)
            #pragma unroll
            for (int c = 0; c < 4; c++) acc[mi][ni][c] = 0;

    #pragma unroll
    for (int s = 0; s < 2; s++) {
        uint32_t Ab = sb + s * STAGE_BYTES, Bb = Ab + ASTAGE;
        #pragma unroll
        for (int i = 0; i < 4; i++) {
            cp16(Ab + ad[i], a_gsrc + s * BKB + i * 16);
            cp16(Bb + ad[i], b_gsrc + s * BKB + i * 16);
        }
        asm volatile("cp.async.commit_group;" ::: "memory");
    }

    for (int kc = 0; kc < NKC; kc++) {
        if (kc == NKC - 1) asm volatile("cp.async.wait_group 0;" ::: "memory");
        else               asm volatile("cp.async.wait_group 1;" ::: "memory");
        __syncthreads();
        if (kc + 2 < NKC) {
            uint32_t Ab = sb + ((kc + 2) % NSTAGE) * STAGE_BYTES, Bb = Ab + ASTAGE;
            const char* as = a_gsrc + (size_t)(kc + 2) * BKB;
            const char* bs = b_gsrc + (size_t)(kc + 2) * BKB;
            #pragma unroll
            for (int i = 0; i < 4; i++) {
                cp16(Ab + ad[i], as + i * 16);
                cp16(Bb + ad[i], bs + i * 16);
            }
            asm volatile("cp.async.commit_group;" ::: "memory");
        }
        const uint32_t Ab = sb + (kc % NSTAGE) * STAGE_BYTES, Bb = Ab + ASTAGE;
        const int lrow = (lane & 7) + ((lane >> 3) & 1) * 8;
        #pragma unroll
        for (int ks = 0; ks < 4; ks++) {
            const int lchk = ks * 2 + (lane >> 4);
            uint32_t a[2][4];
            #pragma unroll
            for (int mi = 0; mi < 2; mi++)
                ldm_x4(a[mi], Ab + swz(wm * 32 + mi * 16 + lrow, lchk));
            uint32_t b0[4][2];
            #pragma unroll
            for (int np = 0; np < 2; np++) {
                uint32_t t4[4];
                ldm_x4(t4, Bb + swz(wn * 64 + np * 16 + lrow, lchk));
                b0[np * 2][0]     = t4[0]; b0[np * 2][1]     = t4[2];
                b0[np * 2 + 1][0] = t4[1]; b0[np * 2 + 1][1] = t4[3];
            }
            #pragma unroll
            for (int mi = 0; mi < 2; mi++)
                #pragma unroll
                for (int ni = 0; ni < 4; ni++)
                    mma_s8(acc[mi][ni], a[mi], b0[ni]);
            uint32_t b1[4][2];
            #pragma unroll
            for (int np = 0; np < 2; np++) {
                uint32_t t4[4];
                ldm_x4(t4, Bb + swz(wn * 64 + 32 + np * 16 + lrow, lchk));
                b1[np * 2][0]     = t4[0]; b1[np * 2][1]     = t4[2];
                b1[np * 2 + 1][0] = t4[1]; b1[np * 2 + 1][1] = t4[3];
            }
            #pragma unroll
            for (int mi = 0; mi < 2; mi++)
                #pragma unroll
                for (int ni = 0; ni < 4; ni++)
                    mma_s8(acc[mi][ni + 4], a[mi], b1[ni]);
        }
    }

    // ---- epilogue: dequant, exp, per-row (+col) sums ----
    __syncthreads();
    if (tid < BM) { red[tid] = 0.f; cred[tid] = 0.f; }
    __syncthreads();
    const int rloc = wm * 32 + (lane >> 2);
    const int cloc = wn * 64 + 2 * (lane & 3);
    float sj[16];
    #pragma unroll
    for (int ni = 0; ni < 8; ni++) {
        sj[ni * 2]     = sCS[cloc + ni * 8];
        sj[ni * 2 + 1] = sCS[cloc + ni * 8 + 1];
    }
    float ccol[16];
    #pragma unroll
    for (int t = 0; t < 16; t++) ccol[t] = 0.f;

    if (!hasmask) {
        #pragma unroll
        for (int mi = 0; mi < 2; mi++) {
            #pragma unroll
            for (int h = 0; h < 2; h++) {
                const int il = rloc + mi * 16 + h * 8;
                const float si = sRS[il];
                float e = 0.f;
                #pragma unroll
                for (int ni = 0; ni < 8; ni++) {
                    #pragma unroll
                    for (int q = 0; q < 2; q++) {
                        float ex = __expf((float)acc[mi][ni][h * 2 + q] * (si * sj[ni * 2 + q]));
                        e += ex;
                        ccol[ni * 2 + q] += ex;
                    }
                }
                e += __shfl_xor_sync(0xffffffffu, e, 1);
                e += __shfl_xor_sync(0xffffffffu, e, 2);
                if ((lane & 3) == 0) atomicAdd(&red[il], e);
            }
        }
        #pragma unroll
        for (int ni = 0; ni < 8; ni++) {
            #pragma unroll
            for (int q = 0; q < 2; q++) {
                float c = ccol[ni * 2 + q];
                c += __shfl_xor_sync(0xffffffffu, c, 4);
                c += __shfl_xor_sync(0xffffffffu, c, 8);
                c += __shfl_xor_sync(0xffffffffu, c, 16);
                if ((lane >> 2) == 0)
                    atomicAdd(&cred[wn * 64 + ni * 8 + 2 * lane + q], c);
            }
        }
    } else {
        #pragma unroll
        for (int mi = 0; mi < 2; mi++) {
            #pragma unroll
            for (int h = 0; h < 2; h++) {
                const int il = rloc + mi * 16 + h * 8;
                const int i  = row0 + il;
                const float si = sRS[il];
                float e = 0.f;
                #pragma unroll
                for (int ni = 0; ni < 8; ni++) {
                    #pragma unroll
                    for (int q = 0; q < 2; q++) {
                        const int j = col0 + cloc + ni * 8 + q;
                        float s = (float)acc[mi][ni][h * 2 + q] * (si * sj[ni * 2 + q]);
                        float ex = (((i ^ j) & (NS - 1)) != 0) ? __expf(s) : 0.f;
                        e += ex;
                        ccol[ni * 2 + q] += ex;
                    }
                }
                e += __shfl_xor_sync(0xffffffffu, e, 1);
                e += __shfl_xor_sync(0xffffffffu, e, 2);
                if ((lane & 3) == 0) atomicAdd(&red[il], e);
            }
        }
        if (offdiag) {
            #pragma unroll
            for (int ni = 0; ni < 8; ni++) {
                #pragma unroll
                for (int q = 0; q < 2; q++) {
                    float c = ccol[ni * 2 + q];
                    c += __shfl_xor_sync(0xffffffffu, c, 4);
                    c += __shfl_xor_sync(0xffffffffu, c, 8);
                    c += __shfl_xor_sync(0xffffffffu, c, 16);
                    if ((lane >> 2) == 0)
                        atomicAdd(&cred[wn * 64 + ni * 8 + 2 * lane + q], c);
                }
            }
        }
    }
    __syncthreads();
    if (tid < BM) {
        atomicAdd(&g_row_exp[row0 + tid], red[tid]);
        if (offdiag) atomicAdd(&g_row_exp[col0 + tid], cred[tid]);
    }
}

// ---------------- kernel 3: finalize (128 thr, grid 1024; output + reset) ---
__global__ void final_row_kernel(const float* __restrict__ x1, const float* __restrict__ x2,
                                 float* __restrict__ out) {
    __shared__ float4 sS[DIM / 4];
    __shared__ float r[24];
    __shared__ int last;
    const int tid = threadIdx.x, wid = tid >> 5, lane = tid & 31;
    sS[tid] = ((const float4*)g_S)[tid];
    __syncthreads();

    const int r0 = blockIdx.x * 8 + wid * 2;
    const float4* xa = (const float4*)row_ptr(x1, x2, r0);
    const float4* xb = (const float4*)row_ptr(x1, x2, r0 + 1);
    float da = 0.f, db = 0.f;
    #pragma unroll
    for (int c = 0; c < 4; c++) {
        float4 va = xa[lane + 32 * c];
        float4 vb = xb[lane + 32 * c];
        float4 sc = sS[lane + 32 * c];
        da += va.x * sc.x + va.y * sc.y + va.z * sc.z + va.w * sc.w;
        db += vb.x * sc.x + vb.y * sc.y + vb.z * sc.z + vb.w * sc.w;
    }
    #pragma unroll
    for (int o = 16; o; o >>= 1) {
        da += __shfl_xor_sync(0xffffffffu, da, o);
        db += __shfl_xor_sync(0xffffffffu, db, o);
    }
    if (lane == 0) {
        float L = 0.f, P = 0.f, NN = 0.f;
        #pragma unroll
        for (int t = 0; t < 2; t++) {
            int row = r0 + t;
            float d  = (t ? db : da) * g_inv_norm[row] * SQRT2F;   // y_i . S
            float sp = 2.0f * g_posdot[row & (NS - 1)] * g_inv_norm[row] * g_inv_norm[row ^ NS];
            float denom = __expf(sp) + g_row_exp[row] + 2.0f;      // +2 = masked exp(0)s
            L  += __logf(denom) - sp;
            P  += sp;
            NN += d - 2.0f - sp;   // s_ii = 2 exactly; exclude positive pair
        }
        r[wid] = L; r[8 + wid] = P; r[16 + wid] = NN;
    }
    __syncthreads();
    if (tid == 0) {
        float L = 0.f, P = 0.f, NN = 0.f;
        #pragma unroll
        for (int k = 0; k < 4; k++) { L += r[k]; P += r[8 + k]; NN += r[16 + k]; }
        atomicAdd(&g_acc[0], L);
        atomicAdd(&g_acc[1], P);
        atomicAdd(&g_acc[2], NN);
        __threadfence();
        unsigned int prev = atomicAdd(&g_done, 1u);
        last = (prev == (unsigned int)(gridDim.x - 1)) ? 1 : 0;
    }
    __syncthreads();
    if (last) {
        if (tid == 0) {
            out[0] = g_acc[0] / (float)NTOT;
            out[1] = g_acc[1] / (float)NTOT;
            out[2] = g_acc[2] / (float)((double)NTOT * (double)NTOT - 2.0 * (double)NTOT);
            g_acc[0] = 0.f; g_acc[1] = 0.f; g_acc[2] = 0.f;
            g_done = 0u;
        }
        for (int c = tid; c < DIM; c += 128) g_S[c] = 0.f;   // reset for next replay
    }
}

extern "C" void kernel_launch(void* const* d_in, const int* in_sizes, int n_in,
                              void* d_out, int out_size) {
    const float* x1 = (const float*)d_in[0];
    const float* x2 = (const float*)d_in[1];
    cudaFuncSetAttribute(gemm_kernel, cudaFuncAttributeMaxDynamicSharedMemorySize, SMEM_DYN);
    prep_kernel<<<NS / 8, 256>>>(x1, x2);
    gemm_kernel<<<NTILE, 256, SMEM_DYN>>>();
    final_row_kernel<<<NTOT / 8, 128>>>(x1, x2, (float*)d_out);
}

// round 17
// speedup vs baseline: 2.2503x; 2.2503x over previous
#include <cuda_runtime.h>
#include <cuda_bf16.h>
#include <cuda_fp16.h>
#include <cstdint>
#include <math.h>

#define NS    4096
#define NTOT  8192
#define DIM   512
#define BM    128
#define BN    128
#define BKB   128             // k-chunk in bytes (= 128 fp8 elems)
#define NKC   (DIM / BKB)     // 4 k-chunks
#define SQRT2F 1.41421356237f
#define ASTAGE 16384          // 128 rows * 128B
#define STAGE_BYTES (2 * ASTAGE)
#define NSTAGE 2
#define SMEM_DYN (NSTAGE * STAGE_BYTES)   // 64KB -> 3 CTAs/SM
#define NOFF  (64 * 63 / 2)   // strict lower-triangular (off-diag) tiles: 2016
#define NTILE (NOFF + 64)     // + 64 diagonal tiles, scheduled LAST

// ---------------- scratch (__device__ globals; no allocation allowed) -------
__device__ __align__(16) uint8_t g_Yq[NTOT * DIM];   // e4m3(normalized * sqrt2)
__device__ float g_inv_norm[NTOT];
__device__ float g_row_exp[NTOT];
__device__ float g_posdot[NS];
__device__ float g_S[DIM];          // zeroed by previous call's tail (static-init 0 first)
__device__ float g_acc[2];          // L, P accumulators; idem
__device__ unsigned int g_done;     // idem

// ---------------- PTX helpers (baseline PTX only) ---------------------------
__device__ __forceinline__ uint32_t smem_u32(const void* p) {
    uint32_t a;
    asm("{ .reg .u64 t; cvta.to.shared.u64 t, %1; cvt.u32.u64 %0, t; }" : "=r"(a) : "l"(p));
    return a;
}
__device__ __forceinline__ void cp16(uint32_t dst, const void* src) {
    asm volatile("cp.async.cg.shared.global [%0], [%1], 16;" :: "r"(dst), "l"(src) : "memory");
}
__device__ __forceinline__ void ldm_x4(uint32_t* r, uint32_t addr) {
    asm volatile("ldmatrix.sync.aligned.m8n8.x4.shared.b16 {%0,%1,%2,%3}, [%4];"
                 : "=r"(r[0]), "=r"(r[1]), "=r"(r[2]), "=r"(r[3]) : "r"(addr));
}
// fp8 MMA with f16 accumulators (halves accumulator registers)
__device__ __forceinline__ void mma_fp8_h(uint32_t* d, const uint32_t* a, const uint32_t* b) {
    asm volatile(
        "mma.sync.aligned.m16n8k32.row.col.f16.e4m3.e4m3.f16 "
        "{%0,%1}, {%2,%3,%4,%5}, {%6,%7}, {%0,%1};"
        : "+r"(d[0]), "+r"(d[1])
        : "r"(a[0]), "r"(a[1]), "r"(a[2]), "r"(a[3]), "r"(b[0]), "r"(b[1]));
}
__device__ __forceinline__ uint16_t f2_e4m3x2(float lo, float hi) {
    uint16_t r;
    asm("cvt.rn.satfinite.e4m3x2.f32 %0, %1, %2;" : "=h"(r) : "f"(hi), "f"(lo));
    return r;
}
// SW128 swizzle for 128B rows: row r, 16B chunk c (0..7). Bank16 = c ^ (r&7):
// distinct across any 8 consecutive rows -> conflict-free ldmatrix phases.
__device__ __forceinline__ uint32_t swz(int r, int c) {
    return (uint32_t)(r * 128 + ((c ^ (r & 7)) << 4));
}
__device__ __forceinline__ const float* row_ptr(const float* x1, const float* x2, int r) {
    return (r < NS) ? (x1 + (size_t)r * DIM) : (x2 + (size_t)(r - NS) * DIM);
}

// ---------------- kernel 1: norms + fp8 Y + posdot + fused colsum -----------
// (R15 version, verbatim: one sample per warp; rows (s, s+NS) read once.)
__global__ void prep_kernel(const float* __restrict__ x1, const float* __restrict__ x2) {
    __shared__ float sY[16][DIM];
    const int wid  = threadIdx.x >> 5;
    const int lane = threadIdx.x & 31;
    const int s    = blockIdx.x * 8 + wid;          // sample 0..4095

    const float4* xa = (const float4*)(x1 + (size_t)s * DIM);
    const float4* xb = (const float4*)(x2 + (size_t)s * DIM);
    float4 va[4], vb[4];
    #pragma unroll
    for (int c = 0; c < 4; c++) {
        va[c] = xa[lane + 32 * c];
        vb[c] = xb[lane + 32 * c];
    }
    float sa = 0.f, sb = 0.f, pd = 0.f;
    #pragma unroll
    for (int c = 0; c < 4; c++) {
        sa += va[c].x * va[c].x + va[c].y * va[c].y + va[c].z * va[c].z + va[c].w * va[c].w;
        sb += vb[c].x * vb[c].x + vb[c].y * vb[c].y + vb[c].z * vb[c].z + vb[c].w * vb[c].w;
        pd += va[c].x * vb[c].x + va[c].y * vb[c].y + va[c].z * vb[c].z + va[c].w * vb[c].w;
    }
    #pragma unroll
    for (int o = 16; o; o >>= 1) {
        sa += __shfl_xor_sync(0xffffffffu, sa, o);
        sb += __shfl_xor_sync(0xffffffffu, sb, o);
        pd += __shfl_xor_sync(0xffffffffu, pd, o);
    }
    float inva = rsqrtf(sa), invb = rsqrtf(sb);
    if (lane == 0) {
        g_inv_norm[s]      = inva;
        g_inv_norm[s + NS] = invb;
        g_row_exp[s]       = 0.f;
        g_row_exp[s + NS]  = 0.f;
        g_posdot[s]        = pd;
    }
    inva = __shfl_sync(0xffffffffu, inva, 0);
    invb = __shfl_sync(0xffffffffu, invb, 0);
    const float ka = inva * SQRT2F, kb = invb * SQRT2F;
    uint32_t* ya = (uint32_t*)(g_Yq + (size_t)s * DIM);
    uint32_t* yb = (uint32_t*)(g_Yq + (size_t)(s + NS) * DIM);
    float4* s4a = (float4*)sY[wid * 2];
    float4* s4b = (float4*)sY[wid * 2 + 1];
    #pragma unroll
    for (int c = 0; c < 4; c++) {
        float4 yA = make_float4(va[c].x * ka, va[c].y * ka, va[c].z * ka, va[c].w * ka);
        float4 yB = make_float4(vb[c].x * kb, vb[c].y * kb, vb[c].z * kb, vb[c].w * kb);
        s4a[lane + 32 * c] = yA;
        s4b[lane + 32 * c] = yB;
        ya[lane + 32 * c] = (uint32_t)f2_e4m3x2(yA.x, yA.y) | ((uint32_t)f2_e4m3x2(yA.z, yA.w) << 16);
        yb[lane + 32 * c] = (uint32_t)f2_e4m3x2(yB.x, yB.y) | ((uint32_t)f2_e4m3x2(yB.z, yB.w) << 16);
    }
    __syncthreads();
    #pragma unroll
    for (int col = threadIdx.x; col < DIM; col += 256) {
        float t = 0.f;
        #pragma unroll
        for (int r = 0; r < 16; r++) t += sY[r][col];
        atomicAdd(&g_S[col], t);
    }
}

// ---------------- kernel 2: fp8 GEMM (f16 accum), occ-3, 2-stage ------------
// (R15 version, verbatim)
__global__ __launch_bounds__(256, 3) void gemm_kernel() {
    extern __shared__ __align__(128) char smem[];
    __shared__ float red[BM];
    __shared__ float cred[BN];
    const uint32_t sb = smem_u32(smem);
    const int tid  = threadIdx.x, lane = tid & 31, wid = tid >> 5;
    const int wm   = wid & 3, wn = wid >> 2;

    const int k = blockIdx.x;
    int bx, by;
    const bool offdiag = (k < NOFF);
    if (offdiag) {
        bx = (int)((sqrtf(8.0f * (float)k + 1.0f) + 1.0f) * 0.5f);
        while (bx * (bx - 1) / 2 > k)        bx--;
        while ((bx + 1) * bx / 2 <= k)       bx++;
        by = k - bx * (bx - 1) / 2;
    } else {
        bx = by = k - NOFF;
    }
    const int row0 = by * BM, col0 = bx * BN;
    const bool hasmask = (((bx ^ by) & 31) == 0);

    const int lr  = tid >> 1;
    const int lc0 = (tid & 1) * 4;
    const char* a_gsrc = (const char*)(g_Yq + (size_t)(row0 + lr) * DIM) + lc0 * 16;
    const char* b_gsrc = (const char*)(g_Yq + (size_t)(col0 + lr) * DIM) + lc0 * 16;
    uint32_t ad[4];
    #pragma unroll
    for (int i = 0; i < 4; i++) ad[i] = swz(lr, lc0 + i);

    uint32_t acc[2][8][2];   // f16x2 accumulators
    #pragma unroll
    for (int mi = 0; mi < 2; mi++)
        #pragma unroll
        for (int ni = 0; ni < 8; ni++) { acc[mi][ni][0] = 0u; acc[mi][ni][1] = 0u; }

    {
        uint32_t Ab = sb, Bb = sb + ASTAGE;
        #pragma unroll
        for (int i = 0; i < 4; i++) {
            cp16(Ab + ad[i], a_gsrc + i * 16);
            cp16(Bb + ad[i], b_gsrc + i * 16);
        }
        asm volatile("cp.async.commit_group;" ::: "memory");
    }

    for (int kc = 0; kc < NKC; kc++) {
        if (kc + 1 < NKC) {
            uint32_t Ab = sb + ((kc + 1) & 1) * STAGE_BYTES, Bb = Ab + ASTAGE;
            const char* as = a_gsrc + (size_t)(kc + 1) * BKB;
            const char* bs = b_gsrc + (size_t)(kc + 1) * BKB;
            #pragma unroll
            for (int i = 0; i < 4; i++) {
                cp16(Ab + ad[i], as + i * 16);
                cp16(Bb + ad[i], bs + i * 16);
            }
            asm volatile("cp.async.commit_group;" ::: "memory");
            asm volatile("cp.async.wait_group 1;" ::: "memory");
        } else {
            asm volatile("cp.async.wait_group 0;" ::: "memory");
        }
        __syncthreads();

        const uint32_t Ab = sb + (kc & 1) * STAGE_BYTES, Bb = Ab + ASTAGE;
        const int lrow = (lane & 7) + ((lane >> 3) & 1) * 8;
        #pragma unroll
        for (int ks = 0; ks < 4; ks++) {
            const int lchk = ks * 2 + (lane >> 4);
            uint32_t a[2][4];
            #pragma unroll
            for (int mi = 0; mi < 2; mi++)
                ldm_x4(a[mi], Ab + swz(wm * 32 + mi * 16 + lrow, lchk));
            uint32_t b0[4][2];
            #pragma unroll
            for (int np = 0; np < 2; np++) {
                uint32_t t4[4];
                ldm_x4(t4, Bb + swz(wn * 64 + np * 16 + lrow, lchk));
                b0[np * 2][0]     = t4[0]; b0[np * 2][1]     = t4[2];
                b0[np * 2 + 1][0] = t4[1]; b0[np * 2 + 1][1] = t4[3];
            }
            #pragma unroll
            for (int mi = 0; mi < 2; mi++)
                #pragma unroll
                for (int ni = 0; ni < 4; ni++)
                    mma_fp8_h(acc[mi][ni], a[mi], b0[ni]);
            uint32_t b1[4][2];
            #pragma unroll
            for (int np = 0; np < 2; np++) {
                uint32_t t4[4];
                ldm_x4(t4, Bb + swz(wn * 64 + 32 + np * 16 + lrow, lchk));
                b1[np * 2][0]     = t4[0]; b1[np * 2][1]     = t4[2];
                b1[np * 2 + 1][0] = t4[1]; b1[np * 2 + 1][1] = t4[3];
            }
            #pragma unroll
            for (int mi = 0; mi < 2; mi++)
                #pragma unroll
                for (int ni = 0; ni < 4; ni++)
                    mma_fp8_h(acc[mi][ni + 4], a[mi], b1[ni]);
        }
        __syncthreads();
    }

    // ---- epilogue ----
    if (tid < BM) { red[tid] = 0.f; cred[tid] = 0.f; }
    __syncthreads();
    const int rloc  = wm * 32 + (lane >> 2);
    const int cbase = col0 + wn * 64 + 2 * (lane & 3);
    float ccol[16];
    #pragma unroll
    for (int t = 0; t < 16; t++) ccol[t] = 0.f;

    if (!hasmask) {
        #pragma unroll
        for (int mi = 0; mi < 2; mi++) {
            #pragma unroll
            for (int h = 0; h < 2; h++) {
                const int il = rloc + mi * 16 + h * 8;
                float e = 0.f;
                #pragma unroll
                for (int ni = 0; ni < 8; ni++) {
                    float2 v = __half22float2(*(const __half2*)&acc[mi][ni][h]);
                    float ex0 = __expf(v.x), ex1 = __expf(v.y);
                    e += ex0 + ex1;
                    ccol[ni * 2]     += ex0;
                    ccol[ni * 2 + 1] += ex1;
                }
                e += __shfl_xor_sync(0xffffffffu, e, 1);
                e += __shfl_xor_sync(0xffffffffu, e, 2);
                if ((lane & 3) == 0) atomicAdd(&red[il], e);
            }
        }
        #pragma unroll
        for (int ni = 0; ni < 8; ni++) {
            #pragma unroll
            for (int q = 0; q < 2; q++) {
                float c = ccol[ni * 2 + q];
                c += __shfl_xor_sync(0xffffffffu, c, 4);
                c += __shfl_xor_sync(0xffffffffu, c, 8);
                c += __shfl_xor_sync(0xffffffffu, c, 16);
                if ((lane >> 2) == 0)
                    atomicAdd(&cred[wn * 64 + ni * 8 + 2 * lane + q], c);
            }
        }
    } else {
        #pragma unroll
        for (int mi = 0; mi < 2; mi++) {
            #pragma unroll
            for (int h = 0; h < 2; h++) {
                const int il = rloc + mi * 16 + h * 8;
                const int i  = row0 + il;
                float e = 0.f;
                #pragma unroll
                for (int ni = 0; ni < 8; ni++) {
                    float2 v = __half22float2(*(const __half2*)&acc[mi][ni][h]);
                    const int j0 = cbase + ni * 8;
                    float ex0 = (((i ^ j0) & (NS - 1)) != 0)       ? __expf(v.x) : 0.f;
                    float ex1 = (((i ^ (j0 + 1)) & (NS - 1)) != 0) ? __expf(v.y) : 0.f;
                    e += ex0 + ex1;
                    ccol[ni * 2]     += ex0;
                    ccol[ni * 2 + 1] += ex1;
                }
                e += __shfl_xor_sync(0xffffffffu, e, 1);
                e += __shfl_xor_sync(0xffffffffu, e, 2);
                if ((lane & 3) == 0) atomicAdd(&red[il], e);
            }
        }
        if (offdiag) {
            #pragma unroll
            for (int ni = 0; ni < 8; ni++) {
                #pragma unroll
                for (int q = 0; q < 2; q++) {
                    float c = ccol[ni * 2 + q];
                    c += __shfl_xor_sync(0xffffffffu, c, 4);
                    c += __shfl_xor_sync(0xffffffffu, c, 8);
                    c += __shfl_xor_sync(0xffffffffu, c, 16);
                    if ((lane >> 2) == 0)
                        atomicAdd(&cred[wn * 64 + ni * 8 + 2 * lane + q], c);
                }
            }
        }
    }
    __syncthreads();
    if (tid < BM) {
        atomicAdd(&g_row_exp[row0 + tid], red[tid]);
        if (offdiag) atomicAdd(&g_row_exp[col0 + tid], cred[tid]);
    }
}

// ---------------- kernel 3: finalize (no x reads; global neg-sim identity) --
// Per row: loss from row_exp/posdot. Total neg-sim = S.S - 2*NTOT - P
// (sum over all pairs = colsum dot itself; subtract diagonal and positives).
__global__ void final_kernel(float* __restrict__ out) {
    __shared__ float r[32];
    __shared__ int last;
    const int tid = threadIdx.x, wid = tid >> 5, lane = tid & 31;
    const int row = blockIdx.x * 512 + tid;

    float sp = 2.0f * g_posdot[row & (NS - 1)] * g_inv_norm[row] * g_inv_norm[row ^ NS];
    float denom = __expf(sp) + g_row_exp[row] + 2.0f;   // +2 = masked exp(0)s
    float l = __logf(denom) - sp;
    #pragma unroll
    for (int o = 16; o; o >>= 1) {
        l  += __shfl_xor_sync(0xffffffffu, l, o);
        sp += __shfl_xor_sync(0xffffffffu, sp, o);
    }
    if (lane == 0) { r[wid] = l; r[16 + wid] = sp; }
    __syncthreads();
    if (tid == 0) {
        float L = 0.f, P = 0.f;
        #pragma unroll
        for (int k = 0; k < 16; k++) { L += r[k]; P += r[16 + k]; }
        atomicAdd(&g_acc[0], L);
        atomicAdd(&g_acc[1], P);
        __threadfence();
        unsigned int prev = atomicAdd(&g_done, 1u);
        last = (prev == (unsigned int)(gridDim.x - 1)) ? 1 : 0;
    }
    __syncthreads();
    if (last) {
        // S.S over 512 elements with the block's first 512 threads (tid==col)
        float v = g_S[tid];
        float ss = v * v;
        #pragma unroll
        for (int o = 16; o; o >>= 1) ss += __shfl_xor_sync(0xffffffffu, ss, o);
        if (lane == 0) r[wid] = ss;
        __syncthreads();
        if (tid == 0) {
            float SS = 0.f;
            #pragma unroll
            for (int k = 0; k < 16; k++) SS += r[k];
            float P = g_acc[1];
            out[0] = g_acc[0] / (float)NTOT;
            out[1] = P / (float)NTOT;
            out[2] = (SS - 2.0f * (float)NTOT - P)
                     / (float)((double)NTOT * (double)NTOT - 2.0 * (double)NTOT);
            g_acc[0] = 0.f; g_acc[1] = 0.f;
            g_done = 0u;
        }
        __syncthreads();
        g_S[tid] = 0.f;    // reset for next replay (512 threads = DIM)
    }
}

extern "C" void kernel_launch(void* const* d_in, const int* in_sizes, int n_in,
                              void* d_out, int out_size) {
    const float* x1 = (const float*)d_in[0];
    const float* x2 = (const float*)d_in[1];
    cudaFuncSetAttribute(gemm_kernel, cudaFuncAttributeMaxDynamicSharedMemorySize, SMEM_DYN);
    prep_kernel<<<NS / 8, 256>>>(x1, x2);
    gemm_kernel<<<NTILE, 256, SMEM_DYN>>>();
    final_kernel<<<NTOT / 512, 512>>>((float*)d_out);
}